// round 16
// baseline (speedup 1.0000x reference)
#include <cuda_runtime.h>

// hidden [4096] f32, encoder_outputs [8192,1,4096] f32
// energies = enc @ hidden -> softmax -> output = enc^T @ attn
// d_out: [0:4096) = output, [4096:12288) = attn
//
// pass1: 512 blocks x 16 rows; after writing its partial, the LAST block of
//        each 16-block chunk folds the chunk's partials (L2-hot) into one
//        level-2 partial with chunk-local softmax merge.
// combine: touches only 32 level-2 partials (512 KB): direct column writes
//          (no atomics) + attn; stats recomputed from 64 floats per block.

#define SEQ_LEN 8192
#define HIDDEN  4096
#define H4      (HIDDEN / 4)
#define NBLK    512
#define ROWS    16                 // rows per pass1 block
#define GRP     4                  // rows per inner group
#define NGRP    (ROWS / GRP)       // 4
#define CH      16                 // pass1 blocks per fold chunk
#define NCHUNK  (NBLK / CH)        // 32

__device__ float g_energies[SEQ_LEN];
__device__ float g_partial[(size_t)NBLK * HIDDEN];
__device__ float g_m[NBLK];
__device__ float g_l[NBLK];
__device__ float g_partial2[(size_t)NCHUNK * HIDDEN];
__device__ float g_m2[NCHUNK];
__device__ float g_l2[NCHUNK];
__device__ int   g_ccount[NCHUNK];   // zero-init; reset by each folder

// ---------------------------------------------------------------------------
__global__ __launch_bounds__(256, 2) void pass1(
    const float* __restrict__ enc, const float* __restrict__ hidden)
{
    const int tid  = threadIdx.x;
    const int wid  = tid >> 5;
    const int lane = tid & 31;
    const int r0   = blockIdx.x * ROWS;
    const int chunk = blockIdx.x / CH;

    __shared__ float sred[2][GRP][8];
    __shared__ int   s_last;

    const float4* h4 = reinterpret_cast<const float4*>(hidden);
    float4 hv0 = h4[tid];
    float4 hv1 = h4[tid + 256];
    float4 hv2 = h4[tid + 512];
    float4 hv3 = h4[tid + 768];

    float4 acc[4];
    #pragma unroll
    for (int k = 0; k < 4; ++k) acc[k] = make_float4(0.f, 0.f, 0.f, 0.f);
    float m = -3.4e38f;
    float l = 0.f;

    #pragma unroll 1
    for (int g = 0; g < NGRP; ++g) {
        const int rg = r0 + g * GRP;

        float4 d[GRP][4];
        #pragma unroll
        for (int s = 0; s < GRP; ++s) {
            const float4* b = reinterpret_cast<const float4*>(enc + (size_t)(rg + s) * HIDDEN);
            d[s][0] = __ldcs(b + tid);
            d[s][1] = __ldcs(b + tid + 256);
            d[s][2] = __ldcs(b + tid + 512);
            d[s][3] = __ldcs(b + tid + 768);
        }

        float dot[GRP];
        #pragma unroll
        for (int s = 0; s < GRP; ++s) {
            dot[s] = d[s][0].x*hv0.x + d[s][0].y*hv0.y + d[s][0].z*hv0.z + d[s][0].w*hv0.w
                   + d[s][1].x*hv1.x + d[s][1].y*hv1.y + d[s][1].z*hv1.z + d[s][1].w*hv1.w
                   + d[s][2].x*hv2.x + d[s][2].y*hv2.y + d[s][2].z*hv2.z + d[s][2].w*hv2.w
                   + d[s][3].x*hv3.x + d[s][3].y*hv3.y + d[s][3].z*hv3.z + d[s][3].w*hv3.w;
        }
        #pragma unroll
        for (int off = 16; off > 0; off >>= 1) {
            #pragma unroll
            for (int s = 0; s < GRP; ++s)
                dot[s] += __shfl_down_sync(0xFFFFFFFFu, dot[s], off);
        }
        if (lane == 0) {
            #pragma unroll
            for (int s = 0; s < GRP; ++s) sred[g & 1][s][wid] = dot[s];
        }
        __syncthreads();

        float e[GRP];
        #pragma unroll
        for (int s = 0; s < GRP; ++s)
            e[s] = sred[g & 1][s][0] + sred[g & 1][s][1] + sred[g & 1][s][2] + sred[g & 1][s][3]
                 + sred[g & 1][s][4] + sred[g & 1][s][5] + sred[g & 1][s][6] + sred[g & 1][s][7];
        if (tid < GRP) g_energies[rg + tid] = e[tid];

        float mg = fmaxf(fmaxf(e[0], e[1]), fmaxf(e[2], e[3]));
        float mn = fmaxf(m, mg);
        float sc = __expf(m - mn);
        float p[GRP];
        float ps = 0.f;
        #pragma unroll
        for (int s = 0; s < GRP; ++s) { p[s] = __expf(e[s] - mn); ps += p[s]; }

        #pragma unroll
        for (int k = 0; k < 4; ++k) {
            acc[k].x *= sc; acc[k].y *= sc; acc[k].z *= sc; acc[k].w *= sc;
        }
        #pragma unroll
        for (int s = 0; s < GRP; ++s) {
            #pragma unroll
            for (int k = 0; k < 4; ++k) {
                acc[k].x += p[s] * d[s][k].x;
                acc[k].y += p[s] * d[s][k].y;
                acc[k].z += p[s] * d[s][k].z;
                acc[k].w += p[s] * d[s][k].w;
            }
        }
        l = l * sc + ps;
        m = mn;
    }

    float4* gp = reinterpret_cast<float4*>(g_partial + (size_t)blockIdx.x * HIDDEN);
    gp[tid]       = acc[0];
    gp[tid + 256] = acc[1];
    gp[tid + 512] = acc[2];
    gp[tid + 768] = acc[3];
    if (tid == 0) { g_m[blockIdx.x] = m; g_l[blockIdx.x] = l; }

    // ---- per-chunk ticket: last of the 16 folds the chunk ------------------
    __threadfence();
    __syncthreads();
    if (tid == 0) {
        int t = atomicAdd(&g_ccount[chunk], 1);
        s_last = (t == CH - 1);
    }
    __syncthreads();
    if (!s_last) return;
    if (tid == 0) g_ccount[chunk] = 0;     // reset for next graph replay

    // fold 16 sibling partials (L2-hot) with chunk-local softmax merge
    __shared__ float smb[CH], slb[CH], swb[CH];
    __shared__ float smc;
    if (tid < CH) { smb[tid] = g_m[chunk * CH + tid]; slb[tid] = g_l[chunk * CH + tid]; }
    __syncthreads();
    if (tid == 0) {
        float mc = smb[0];
        #pragma unroll
        for (int j = 1; j < CH; ++j) mc = fmaxf(mc, smb[j]);
        smc = mc;
    }
    __syncthreads();
    const float mc = smc;
    if (tid < CH) swb[tid] = __expf(smb[tid] - mc);
    __syncthreads();

    float4 f0 = make_float4(0.f,0.f,0.f,0.f);
    float4 f1 = f0, f2 = f0, f3 = f0;
    const float4* pb = reinterpret_cast<const float4*>(g_partial) + (size_t)chunk * CH * H4;
    #pragma unroll 4
    for (int j = 0; j < CH; ++j) {
        const float4* row = pb + (size_t)j * H4;
        float wj = swb[j];
        float4 v0 = row[tid];
        float4 v1 = row[tid + 256];
        float4 v2 = row[tid + 512];
        float4 v3 = row[tid + 768];
        f0.x += wj*v0.x; f0.y += wj*v0.y; f0.z += wj*v0.z; f0.w += wj*v0.w;
        f1.x += wj*v1.x; f1.y += wj*v1.y; f1.z += wj*v1.z; f1.w += wj*v1.w;
        f2.x += wj*v2.x; f2.y += wj*v2.y; f2.z += wj*v2.z; f2.w += wj*v2.w;
        f3.x += wj*v3.x; f3.y += wj*v3.y; f3.z += wj*v3.z; f3.w += wj*v3.w;
    }
    float4* g2 = reinterpret_cast<float4*>(g_partial2 + (size_t)chunk * HIDDEN);
    g2[tid]       = f0;
    g2[tid + 256] = f1;
    g2[tid + 512] = f2;
    g2[tid + 768] = f3;
    if (tid == 0) {
        float lc = 0.f;
        #pragma unroll
        for (int j = 0; j < CH; ++j) lc += slb[j] * swb[j];
        g_m2[chunk] = mc;
        g_l2[chunk] = lc;
    }
}

// ---------------------------------------------------------------------------
// combine: blocks [0,16): direct column writes of out (no atomics);
//          blocks [16,48): attn. Each block recomputes M,Z from 64 floats.
__global__ __launch_bounds__(256) void combine(
    float* __restrict__ out, float* __restrict__ attn)
{
    const int tid = threadIdx.x;
    const int gid = blockIdx.x;

    __shared__ float sw[NCHUNK];
    __shared__ float sMZ[2];

    if (tid < 32) {
        float mt = g_m2[tid];
        float mv = mt;
        #pragma unroll
        for (int off = 16; off > 0; off >>= 1)
            mv = fmaxf(mv, __shfl_xor_sync(0xFFFFFFFFu, mv, off));
        // mv = M in all 32 lanes
        float w = __expf(mt - mv);
        float zt = g_l2[tid] * w;
        #pragma unroll
        for (int off = 16; off > 0; off >>= 1)
            zt += __shfl_xor_sync(0xFFFFFFFFu, zt, off);
        float invZ = 1.0f / zt;
        sw[tid] = w * invZ;
        if (tid == 0) { sMZ[0] = mv; sMZ[1] = invZ; }
    }
    __syncthreads();

    if (gid < 16) {
        const int col = gid * 256 + tid;
        float acc = 0.f;
        #pragma unroll 8
        for (int c = 0; c < NCHUNK; ++c)
            acc += g_partial2[(size_t)c * HIDDEN + col] * sw[c];
        out[col] = acc;
    } else {
        const float M    = sMZ[0];
        const float invZ = sMZ[1];
        const int i = (gid - 16) * 256 + tid;
        attn[i] = __expf(g_energies[i] - M) * invZ;
    }
}

extern "C" void kernel_launch(void* const* d_in, const int* in_sizes, int n_in,
                              void* d_out, int out_size)
{
    const float* hidden = (const float*)d_in[0];
    const float* enc    = (const float*)d_in[1];
    float* out  = (float*)d_out;
    float* attn = (float*)d_out + HIDDEN;

    pass1<<<NBLK, 256>>>(enc, hidden);
    combine<<<16 + SEQ_LEN / 256, 256>>>(out, attn);
}